// round 16
// baseline (speedup 1.0000x reference)
#include <cuda_runtime.h>
#include <math.h>
#include <stdint.h>

#define BB 64
#define SS 512
#define BS (BB*SS)
#define LL 16
#define WD 200
#define CD 30
#define FN 4
#define CF 120
#define KW 3
#define DD 320
#define HH 256
#define G4 1024
#define TT 17
#define LC 14

// ---------------- static scratch (no allocs allowed) ----------------
__device__ float d_z[BS * DD];                    // [B*S, 320]
__device__ float d_gx[2][(size_t)SS * BB * G4];   // [dir][S,B,1024]
__device__ float d_hs[2][(size_t)SS * BB * HH];   // [dir][S,B,256]
__device__ float d_h2[16][2][HH * 8];             // [grp][parity][k*8+b] h exchange
__device__ float d_emis[(size_t)BS * TT];         // [B,S,17]
__device__ float d_nd[BB];
__device__ int   d_ctr[16];

__device__ __forceinline__ float sigf(float x) { return 1.0f / (1.0f + expf(-x)); }

__device__ __forceinline__ int acq_load(const int* p) {
    int v;
    asm volatile("ld.global.acquire.gpu.b32 %0,[%1];" : "=r"(v) : "l"(p) : "memory");
    return v;
}
// fire-and-forget release increment (REDG, no return trip, no MEMBAR needed)
__device__ __forceinline__ void red_release_add(int* p, int v) {
    asm volatile("red.release.gpu.global.add.u32 [%0],%1;" :: "l"(p), "r"(v) : "memory");
}

// ---- packed f32x2 helpers (sm_103a FFMA2) ----
__device__ __forceinline__ unsigned long long fdup(float w) {
    unsigned long long d;
    asm("mov.b64 %0, {%1, %1};" : "=l"(d) : "f"(w));
    return d;
}
__device__ __forceinline__ void ffma2(unsigned long long& a, unsigned long long x,
                                      unsigned long long y) {
    asm("fma.rn.f32x2 %0, %1, %2, %0;" : "+l"(a) : "l"(x), "l"(y));
}
__device__ __forceinline__ unsigned long long addx2(unsigned long long a,
                                                    unsigned long long b) {
    unsigned long long r;
    asm("add.rn.f32x2 %0, %1, %2;" : "=l"(r) : "l"(a), "l"(b));
    return r;
}
__device__ __forceinline__ float2 unpk(unsigned long long a) {
    float2 f;
    asm("mov.b64 {%0, %1}, %2;" : "=f"(f.x), "=f"(f.y) : "l"(a));
    return f;
}

// ---------------- embeddings + char CNN + concat (+ ctr reset in block 0) ---------
__global__ void __launch_bounds__(128) k_embed(const int* __restrict__ tok,
                                               const int* __restrict__ ctok,
                                               const float* __restrict__ wemb,
                                               const float* __restrict__ cemb,
                                               const float* __restrict__ convw,
                                               const float* __restrict__ convb) {
    int w = blockIdx.x;  // word = b*S + s
    __shared__ float ce[LL][CD];
    __shared__ int cid[LL];
    int tid = threadIdx.x;
    if (w == 0 && tid < 16) d_ctr[tid] = 0;   // barrier counters reset (pre-lstm)
    if (tid < LL) cid[tid] = ctok[(size_t)w * LL + tid];
    __syncthreads();
    for (int i = tid; i < LL * CD; i += 128) {
        int l = i / CD, c = i % CD;
        ce[l][c] = cemb[cid[l] * CD + c];
    }
    __syncthreads();
    if (tid < CF) {
        int o = tid, ic = o >> 2;
        float w0 = convw[o * 3 + 0], w1 = convw[o * 3 + 1], w2 = convw[o * 3 + 2];
        float m = -1e30f;
#pragma unroll
        for (int t = 0; t < LC; t++) {
            float v = ce[t][ic] * w0 + ce[t + 1][ic] * w1 + ce[t + 2][ic] * w2;
            m = fmaxf(m, v);
        }
        d_z[(size_t)w * DD + WD + o] = m + convb[o];
    }
    const float* wr = wemb + (size_t)tok[w] * WD;
    for (int j = tid; j < WD; j += 128) d_z[(size_t)w * DD + j] = wr[j];
}

// ---------------- input-side GEMM, double-buffered smem, M-packed FFMA2 -----------
// Accumulators packed along M: multiplier (a_{2i}, a_{2i+1}) loads directly as
// 16B from As (no fdup); only the 4 B-values get duplicated (4 movs/kk vs 8).
// Per-output-element accumulation order identical to before -> bit-identical.
__global__ void __launch_bounds__(256, 2) k_gemm_gx(const float* __restrict__ Wf,
                                                    const float* __restrict__ biasf,
                                                    const float* __restrict__ Wb,
                                                    const float* __restrict__ biasb) {
    int dir = blockIdx.z;
    const float* __restrict__ Wm = dir ? Wb : Wf;
    const float* __restrict__ bias = dir ? biasb : biasf;
    float* out = d_gx[dir];
    const float* __restrict__ Z = d_z;

    int mBase = blockIdx.x * 128;
    int nBase = blockIdx.y * 64;

    __shared__ float As[2][16][132];
    __shared__ float Bs[2][16][68];

    int tid = threadIdx.x;
    int ty = tid >> 4;
    int tx = tid & 15;
    int ar = tid >> 2;       // 0..63
    int kq = tid & 3;        // 0..3

    const float* zp0 = Z + (size_t)(mBase + ar) * DD + kq * 4;
    const float* zp1 = Z + (size_t)(mBase + 64 + ar) * DD + kq * 4;
    const float* wp  = Wm + (size_t)(nBase + ar) * DD + kq * 4;

    // acc2[rp][j]: rows (ty*8+2rp, ty*8+2rp+1), column nBase+tx*4+j
    unsigned long long acc2[4][4];
#pragma unroll
    for (int i = 0; i < 4; i++)
#pragma unroll
        for (int j = 0; j < 4; j++) acc2[i][j] = 0ull;

    float4 ra0, ra1, rb;
    // prologue: load tile 0
    ra0 = *(const float4*)(zp0);
    ra1 = *(const float4*)(zp1);
    rb  = *(const float4*)(wp);
    {
        As[0][kq * 4 + 0][ar] = ra0.x; As[0][kq * 4 + 1][ar] = ra0.y;
        As[0][kq * 4 + 2][ar] = ra0.z; As[0][kq * 4 + 3][ar] = ra0.w;
        As[0][kq * 4 + 0][64 + ar] = ra1.x; As[0][kq * 4 + 1][64 + ar] = ra1.y;
        As[0][kq * 4 + 2][64 + ar] = ra1.z; As[0][kq * 4 + 3][64 + ar] = ra1.w;
        Bs[0][kq * 4 + 0][ar] = rb.x; Bs[0][kq * 4 + 1][ar] = rb.y;
        Bs[0][kq * 4 + 2][ar] = rb.z; Bs[0][kq * 4 + 3][ar] = rb.w;
    }
    __syncthreads();

#pragma unroll 1
    for (int it = 0; it < DD / 16; it++) {
        int p = it & 1;
        if (it + 1 < DD / 16) {
            int k0 = 16 * (it + 1);
            ra0 = *(const float4*)(zp0 + k0);
            ra1 = *(const float4*)(zp1 + k0);
            rb  = *(const float4*)(wp + k0);
        }
#pragma unroll
        for (int kk = 0; kk < 16; kk++) {
            // packed row-pairs, direct 16B smem loads (no dup)
            ulonglong2 ap0 = *(const ulonglong2*)&As[p][kk][ty * 8];      // rows 0,1 | 2,3
            ulonglong2 ap1 = *(const ulonglong2*)&As[p][kk][ty * 8 + 4];  // rows 4,5 | 6,7
            float4 bv = *(const float4*)&Bs[p][kk][tx * 4];
            unsigned long long bd0 = fdup(bv.x);
            unsigned long long bd1 = fdup(bv.y);
            unsigned long long bd2 = fdup(bv.z);
            unsigned long long bd3 = fdup(bv.w);
            ffma2(acc2[0][0], ap0.x, bd0); ffma2(acc2[0][1], ap0.x, bd1);
            ffma2(acc2[0][2], ap0.x, bd2); ffma2(acc2[0][3], ap0.x, bd3);
            ffma2(acc2[1][0], ap0.y, bd0); ffma2(acc2[1][1], ap0.y, bd1);
            ffma2(acc2[1][2], ap0.y, bd2); ffma2(acc2[1][3], ap0.y, bd3);
            ffma2(acc2[2][0], ap1.x, bd0); ffma2(acc2[2][1], ap1.x, bd1);
            ffma2(acc2[2][2], ap1.x, bd2); ffma2(acc2[2][3], ap1.x, bd3);
            ffma2(acc2[3][0], ap1.y, bd0); ffma2(acc2[3][1], ap1.y, bd1);
            ffma2(acc2[3][2], ap1.y, bd2); ffma2(acc2[3][3], ap1.y, bd3);
        }
        if (it + 1 < DD / 16) {
            int q = p ^ 1;
            As[q][kq * 4 + 0][ar] = ra0.x; As[q][kq * 4 + 1][ar] = ra0.y;
            As[q][kq * 4 + 2][ar] = ra0.z; As[q][kq * 4 + 3][ar] = ra0.w;
            As[q][kq * 4 + 0][64 + ar] = ra1.x; As[q][kq * 4 + 1][64 + ar] = ra1.y;
            As[q][kq * 4 + 2][64 + ar] = ra1.z; As[q][kq * 4 + 3][64 + ar] = ra1.w;
            Bs[q][kq * 4 + 0][ar] = rb.x; Bs[q][kq * 4 + 1][ar] = rb.y;
            Bs[q][kq * 4 + 2][ar] = rb.z; Bs[q][kq * 4 + 3][ar] = rb.w;
        }
        __syncthreads();
    }

    float bq0 = bias[nBase + tx * 4 + 0], bq1 = bias[nBase + tx * 4 + 1];
    float bq2 = bias[nBase + tx * 4 + 2], bq3 = bias[nBase + tx * 4 + 3];
#pragma unroll
    for (int rp = 0; rp < 4; rp++) {
        float2 c0 = unpk(acc2[rp][0]);
        float2 c1 = unpk(acc2[rp][1]);
        float2 c2 = unpk(acc2[rp][2]);
        float2 c3 = unpk(acc2[rp][3]);
        int m0 = mBase + ty * 8 + 2 * rp;
#pragma unroll
        for (int h = 0; h < 2; h++) {
            int m = m0 + h;
            int b = m >> 9, s = m & 511;
            size_t ro = ((size_t)s * BB + b) * (size_t)G4 + nBase + tx * 4;
            float4 o4;
            o4.x = (h ? c0.y : c0.x) + bq0;
            o4.y = (h ? c1.y : c1.x) + bq1;
            o4.z = (h ? c2.y : c2.x) + bq2;
            o4.w = (h ? c3.y : c3.x) + bq3;
            *(float4*)&out[ro] = o4;
        }
    }
}

// ---------------- BiLSTM: R14 (best verified) — unchanged -------------------------
#define NSL 16
#define KSL 16
__global__ void __launch_bounds__(256, 2)
k_lstm(const float* __restrict__ whf, const float* __restrict__ whb) {
    __shared__ float h_sm[2 * HH * 8];   // [parity][256 k][8 batch]
    __shared__ float g_sm[64 * 8];       // [local gate row][8 batch]
    __shared__ float c_sm[KSL * 8];      // [k*8+b]

    int blk = blockIdx.x;
    int slice = blk & (NSL - 1);
    int grp = blk >> 4;          // 0..15
    int dir = grp >> 3;
    int bg = grp & 7;
    const float* Wd = dir ? whb : whf;
    int tid = threadIdx.x;
    int row = tid >> 2;          // 0..63 local gate row
    int sub = tid & 3;           // k-interleave lane
    int gt = row >> 4;           // gate 0..3
    int kl = row & 15;
    int ks = slice * KSL;
    int gr = gt * 256 + ks + kl; // gate row in [0,1024)
    const float* gxp = d_gx[dir];
    float* hsp = d_hs[dir];
    int b0 = bg * 8;

    // W into registers: w_reg[kk] = W[gr][4*kk + sub]
    float w_reg[64];
    {
        const float* wr = Wd + (size_t)gr * HH + sub;
#pragma unroll
        for (int kk = 0; kk < 64; kk++) w_reg[kk] = __ldg(wr + 4 * kk);
    }
    if (tid < KSL * 8) c_sm[tid] = 0.f;
    __syncthreads();

    // preload gx for step 0 (sub==0 threads hold gxn for their row)
    float gxn[8];
    if (sub == 0) {
        int t0 = dir ? (SS - 1) : 0;
        const float* gxr = gxp + ((size_t)t0 * BB + b0) * G4 + gr;
#pragma unroll
        for (int b = 0; b < 8; b++) gxn[b] = __ldg(gxr + (size_t)b * G4);
    }

    for (int s = 0; s < SS; s++) {
        int t = dir ? (SS - 1 - s) : s;
        unsigned long long a0 = 0ull, a1 = 0ull, a2 = 0ull, a3 = 0ull;

        if (s > 0) {
            int parp = (s & 1) ^ 1;   // parity of step s-1
            // wait for all 16 CTAs of the group to finish step s-1
            if (tid == 0) {
                int tgt = NSL * s;
                while (acq_load(&d_ctr[grp]) < tgt) {}
            }
            __syncthreads();
            // load h(s-1) from L2 into smem (512 float4 by 256 threads)
            {
                const float4* src = (const float4*)(d_h2[grp][parp]);
                float* dst = h_sm + parp * (HH * 8);
                float4 v0 = __ldcg(src + tid);
                float4 v1 = __ldcg(src + tid + 256);
                *(float4*)&dst[tid * 4] = v0;
                *(float4*)&dst[(tid + 256) * 4] = v1;
            }
            __syncthreads();

            const float* hb = h_sm + parp * (HH * 8) + sub * 8;
#pragma unroll
            for (int kk = 0; kk < 64; kk++) {
                unsigned long long wd = fdup(w_reg[kk]);
                const ulonglong2* hp = (const ulonglong2*)(hb + kk * 32);
                ulonglong2 q0 = hp[0];   // batches 0,1 | 2,3
                ulonglong2 q1 = hp[1];   // batches 4,5 | 6,7
                ffma2(a0, q0.x, wd);
                ffma2(a1, q0.y, wd);
                ffma2(a2, q1.x, wd);
                ffma2(a3, q1.y, wd);
            }
            // reduce across the 4 sub lanes (adjacent in warp)
            a0 = addx2(a0, __shfl_xor_sync(0xffffffffu, a0, 1));
            a1 = addx2(a1, __shfl_xor_sync(0xffffffffu, a1, 1));
            a2 = addx2(a2, __shfl_xor_sync(0xffffffffu, a2, 1));
            a3 = addx2(a3, __shfl_xor_sync(0xffffffffu, a3, 1));
            a0 = addx2(a0, __shfl_xor_sync(0xffffffffu, a0, 2));
            a1 = addx2(a1, __shfl_xor_sync(0xffffffffu, a1, 2));
            a2 = addx2(a2, __shfl_xor_sync(0xffffffffu, a2, 2));
            a3 = addx2(a3, __shfl_xor_sync(0xffffffffu, a3, 2));
        }
        if (sub == 0) {
            float2 p0 = unpk(a0), p1 = unpk(a1), p2 = unpk(a2), p3 = unpk(a3);
            float4 v0, v1;
            v0.x = p0.x + gxn[0]; v0.y = p0.y + gxn[1];
            v0.z = p1.x + gxn[2]; v0.w = p1.y + gxn[3];
            v1.x = p2.x + gxn[4]; v1.y = p2.y + gxn[5];
            v1.z = p3.x + gxn[6]; v1.w = p3.y + gxn[7];
            *(float4*)&g_sm[row * 8] = v0;
            *(float4*)&g_sm[row * 8 + 4] = v1;
        }
        __syncthreads();

        // elementwise LSTM cell: 128 tasks (k = tid>>3 in [0,16), b = tid&7)
        int par = s & 1;
        float hv = 0.f;
        if (tid < KSL * 8) {
            int k = tid >> 3;
            int b = tid & 7;
            float gi = g_sm[(0 * KSL + k) * 8 + b];
            float gf = g_sm[(1 * KSL + k) * 8 + b];
            float gg = g_sm[(2 * KSL + k) * 8 + b];
            float go = g_sm[(3 * KSL + k) * 8 + b];
            float c = c_sm[tid];
            float cn = sigf(gf) * c + sigf(gi) * tanhf(gg);
            hv = sigf(go) * tanhf(cn);
            c_sm[tid] = cn;
            __stcg(&d_h2[grp][par][(ks + k) * 8 + b], hv);
        }
        // prefetch next step's gx (independent of the barrier)
        if (sub == 0 && s + 1 < SS) {
            int tn = dir ? (SS - 2 - s) : (s + 1);
            const float* gxr = gxp + ((size_t)tn * BB + b0) * G4 + gr;
#pragma unroll
            for (int b = 0; b < 8; b++) gxn[b] = __ldg(gxr + (size_t)b * G4);
        }
        __syncthreads();   // h2 stores issued by all cell threads before publish
        if (tid == 0) red_release_add(&d_ctr[grp], 1);
        // history write AFTER publish — background stream, never fenced
        if (tid < KSL * 8) {
            int k = tid >> 3;
            int b = tid & 7;
            hsp[((size_t)t * BB + b0 + b) * HH + ks + k] = hv;
        }
    }
}

// ---------------- emissions: concat(hs_f, hs_b) @ cls_w^T + cls_b ----------------
__global__ void __launch_bounds__(256) k_emis(const float* __restrict__ clsw,
                                              const float* __restrict__ clsb) {
    __shared__ float cw[TT * 512];
    __shared__ float cb[32];
    int tid = threadIdx.x;
    for (int i = tid; i < TT * 512; i += 256) cw[i] = clsw[i];
    if (tid < TT) cb[tid] = clsb[tid];
    __syncthreads();

    int warp = tid >> 5, lane = tid & 31;
    int w = blockIdx.x * 8 + warp;
    int b = w >> 9, s = w & 511;
    const float* hf = d_hs[0] + ((size_t)s * BB + b) * HH;
    const float* hb = d_hs[1] + ((size_t)s * BB + b) * HH;
    float hv[16];
#pragma unroll
    for (int i = 0; i < 8; i++) {
        hv[i] = hf[lane + 32 * i];
        hv[8 + i] = hb[lane + 32 * i];
    }
#pragma unroll 1
    for (int o = 0; o < TT; o++) {
        const float* c0 = cw + o * 512;
        float sum = 0.f;
#pragma unroll
        for (int i = 0; i < 8; i++) {
            sum = fmaf(hv[i], c0[lane + 32 * i], sum);
            sum = fmaf(hv[8 + i], c0[256 + lane + 32 * i], sum);
        }
#pragma unroll
        for (int off = 16; off > 0; off >>= 1)
            sum += __shfl_down_sync(0xffffffffu, sum, off);
        if (lane == 0) d_emis[(size_t)w * TT + o] = sum + cb[o];
    }
}

// ---------------- CRF: blocks 0..63 = loss forward, 64..127 = Viterbi decode -------
__global__ void __launch_bounds__(32) k_crf(const int* __restrict__ labels,
                                            const int* __restrict__ mask,
                                            const float* __restrict__ startt,
                                            const float* __restrict__ endt,
                                            const float* __restrict__ trans,
                                            float* __restrict__ tok_out) {
    int which = blockIdx.x >> 6;
    int b = blockIdx.x & 63;
    int ln = threadIdx.x;
    __shared__ float tr[TT * TT];
    __shared__ float al[TT];
    __shared__ unsigned char bp[SS - 1][TT];
    for (int i = ln; i < TT * TT; i += 32) tr[i] = trans[i];
    __syncwarp();

    if (which == 0) {
        // ---- loss ----
        float part = 0.f;
        for (int s = ln; s < SS; s += 32) {
            int tg = labels[(size_t)b * SS + s];
            float mf = (float)mask[(size_t)b * SS + s];
            part += d_emis[((size_t)b * SS + s) * TT + tg] * mf;
            if (s >= 1) {
                int tp = labels[(size_t)b * SS + s - 1];
                part += tr[tp * TT + tg] * mf;
            }
        }
#pragma unroll
        for (int off = 16; off > 0; off >>= 1)
            part += __shfl_down_sync(0xffffffffu, part, off);
        float num = 0.f;
        if (ln == 0) {
            num = part + startt[labels[(size_t)b * SS]];
            int cnt = 0;
            for (int s = 0; s < SS; s++) cnt += mask[(size_t)b * SS + s];
            num += endt[labels[(size_t)b * SS + cnt - 1]];
        }

        if (ln < TT) al[ln] = startt[ln] + d_emis[((size_t)b * SS) * TT + ln];
        __syncwarp();
        for (int s = 1; s < SS; s++) {
            int m = mask[(size_t)b * SS + s];
            float nv = 0.f;
            if (ln < TT) {
                float v[TT];
                float mx = -1e30f;
#pragma unroll
                for (int i = 0; i < TT; i++) {
                    v[i] = al[i] + tr[i * TT + ln];
                    mx = fmaxf(mx, v[i]);
                }
                float sum = 0.f;
#pragma unroll
                for (int i = 0; i < TT; i++) sum += expf(v[i] - mx);
                nv = mx + logf(sum) + d_emis[((size_t)b * SS + s) * TT + ln];
            }
            __syncwarp();
            if (ln < TT && m > 0) al[ln] = nv;
            __syncwarp();
        }
        if (ln == 0) {
            float mx = -1e30f;
            for (int j = 0; j < TT; j++) mx = fmaxf(mx, al[j] + endt[j]);
            float sum = 0.f;
            for (int j = 0; j < TT; j++) sum += expf(al[j] + endt[j] - mx);
            d_nd[b] = num - (mx + logf(sum));
        }
    } else {
        // ---- Viterbi decode ----
        if (ln < TT) al[ln] = startt[ln] + d_emis[((size_t)b * SS) * TT + ln];
        __syncwarp();
        for (int s = 1; s < SS; s++) {
            int m = mask[(size_t)b * SS + s];
            float nv = 0.f;
            int arg = 0;
            if (ln < TT) {
                float mx = -1e30f;
#pragma unroll
                for (int i = 0; i < TT; i++) {
                    float v = al[i] + tr[i * TT + ln];
                    if (v > mx) { mx = v; arg = i; }
                }
                nv = mx + d_emis[((size_t)b * SS + s) * TT + ln];
            }
            __syncwarp();
            if (ln < TT) {
                if (m > 0) { al[ln] = nv; bp[s - 1][ln] = (unsigned char)arg; }
                else bp[s - 1][ln] = (unsigned char)ln;
            }
            __syncwarp();
        }
        if (ln == 0) {
            float mx = -1e30f;
            int lt = 0;
            for (int j = 0; j < TT; j++) {
                float v = al[j] + endt[j];
                if (v > mx) { mx = v; lt = j; }
            }
            tok_out[(size_t)b * SS + (SS - 1)] = (float)lt;
            int tg = lt;
            for (int s = SS - 2; s >= 0; s--) {
                tg = bp[s][tg];
                tok_out[(size_t)b * SS + s] = (float)tg;
            }
        }
    }
}

// ---------------- final loss reduce ----------------
__global__ void __launch_bounds__(64) k_final(float* __restrict__ out) {
    int tid = threadIdx.x;
    float v = d_nd[tid];
#pragma unroll
    for (int off = 16; off > 0; off >>= 1) v += __shfl_down_sync(0xffffffffu, v, off);
    __shared__ float w[2];
    if ((tid & 31) == 0) w[tid >> 5] = v;
    __syncthreads();
    if (tid == 0) out[0] = -(w[0] + w[1]) / (float)BB;
}

// ---------------- launch ----------------
extern "C" void kernel_launch(void* const* d_in, const int* in_sizes, int n_in,
                              void* d_out, int out_size) {
    const int* tok     = (const int*)d_in[0];
    const int* ctok    = (const int*)d_in[1];
    const int* labels  = (const int*)d_in[2];
    const int* amask   = (const int*)d_in[3];
    const float* wemb  = (const float*)d_in[4];
    const float* cemb  = (const float*)d_in[5];
    const float* convw = (const float*)d_in[6];
    const float* convb = (const float*)d_in[7];
    const float* wihf  = (const float*)d_in[8];
    const float* whhf  = (const float*)d_in[9];
    const float* bf    = (const float*)d_in[10];
    const float* wihb  = (const float*)d_in[11];
    const float* whhb  = (const float*)d_in[12];
    const float* bb    = (const float*)d_in[13];
    const float* clsw  = (const float*)d_in[14];
    const float* clsb  = (const float*)d_in[15];
    const float* startt = (const float*)d_in[16];
    const float* endt   = (const float*)d_in[17];
    const float* trans  = (const float*)d_in[18];
    float* out = (float*)d_out;
    int tok_off = out_size - BB * SS;
    if (tok_off < 0) tok_off = 0;

    k_embed<<<BS, 128>>>(tok, ctok, wemb, cemb, convw, convb);
    dim3 gg(BS / 128, G4 / 64, 2);
    k_gemm_gx<<<gg, 256>>>(wihf, bf, wihb, bb);
    k_lstm<<<256, 256>>>(whhf, whhb);
    k_emis<<<BS / 8, 256>>>(clsw, clsb);
    k_crf<<<2 * BB, 32>>>(labels, amask, startt, endt, trans, out + tok_off);
    k_final<<<1, 64>>>(out);
}

// round 17
// speedup vs baseline: 1.0397x; 1.0397x over previous
#include <cuda_runtime.h>
#include <math.h>
#include <stdint.h>

#define BB 64
#define SS 512
#define BS (BB*SS)
#define LL 16
#define WD 200
#define CD 30
#define FN 4
#define CF 120
#define KW 3
#define DD 320
#define HH 256
#define G4 1024
#define TT 17
#define LC 14

// ---------------- static scratch (no allocs allowed) ----------------
__device__ float d_z[BS * DD];                    // [B*S, 320]
__device__ float d_gx[2][(size_t)SS * BB * G4];   // [dir][S,B,1024]
__device__ float d_hs[2][(size_t)SS * BB * HH];   // [dir][S,B,256]
__device__ float d_h2[16][2][HH * 8];             // [grp][parity][k*8+b] h exchange
__device__ float d_emis[(size_t)BS * TT];         // [B,S,17]
__device__ float d_nd[BB];
__device__ int   d_ctr[16];

__device__ __forceinline__ float sigf(float x) { return 1.0f / (1.0f + expf(-x)); }

__device__ __forceinline__ int acq_load(const int* p) {
    int v;
    asm volatile("ld.global.acquire.gpu.b32 %0,[%1];" : "=r"(v) : "l"(p) : "memory");
    return v;
}
// fire-and-forget release increment (REDG, no return trip, no MEMBAR needed)
__device__ __forceinline__ void red_release_add(int* p, int v) {
    asm volatile("red.release.gpu.global.add.u32 [%0],%1;" :: "l"(p), "r"(v) : "memory");
}

// ---- packed f32x2 helpers (sm_103a FFMA2) ----
__device__ __forceinline__ unsigned long long fdup(float w) {
    unsigned long long d;
    asm("mov.b64 %0, {%1, %1};" : "=l"(d) : "f"(w));
    return d;
}
__device__ __forceinline__ void ffma2(unsigned long long& a, unsigned long long x,
                                      unsigned long long y) {
    asm("fma.rn.f32x2 %0, %1, %2, %0;" : "+l"(a) : "l"(x), "l"(y));
}
__device__ __forceinline__ unsigned long long addx2(unsigned long long a,
                                                    unsigned long long b) {
    unsigned long long r;
    asm("add.rn.f32x2 %0, %1, %2;" : "=l"(r) : "l"(a), "l"(b));
    return r;
}
__device__ __forceinline__ float2 unpk(unsigned long long a) {
    float2 f;
    asm("mov.b64 {%0, %1}, %2;" : "=f"(f.x), "=f"(f.y) : "l"(a));
    return f;
}

// ---------------- embeddings + char CNN + concat: 2 words per 256-thread CTA ------
// Two independent 128-thread halves; per-word code identical to the verified
// version; both halves always reach every __syncthreads.
__global__ void __launch_bounds__(256) k_embed(const int* __restrict__ tok,
                                               const int* __restrict__ ctok,
                                               const float* __restrict__ wemb,
                                               const float* __restrict__ cemb,
                                               const float* __restrict__ convw,
                                               const float* __restrict__ convb) {
    int half = threadIdx.x >> 7;
    int tid = threadIdx.x & 127;
    int w = blockIdx.x * 2 + half;    // word = b*S + s
    __shared__ float ce[2][LL][CD];
    __shared__ int cid[2][LL];
    if (w == 0 && tid < 16) d_ctr[tid] = 0;   // barrier counters reset (pre-lstm)
    if (tid < LL) cid[half][tid] = ctok[(size_t)w * LL + tid];
    __syncthreads();
    for (int i = tid; i < LL * CD; i += 128) {
        int l = i / CD, c = i % CD;
        ce[half][l][c] = cemb[cid[half][l] * CD + c];
    }
    __syncthreads();
    if (tid < CF) {
        int o = tid, ic = o >> 2;
        float w0 = convw[o * 3 + 0], w1 = convw[o * 3 + 1], w2 = convw[o * 3 + 2];
        float m = -1e30f;
#pragma unroll
        for (int t = 0; t < LC; t++) {
            float v = ce[half][t][ic] * w0 + ce[half][t + 1][ic] * w1 + ce[half][t + 2][ic] * w2;
            m = fmaxf(m, v);
        }
        d_z[(size_t)w * DD + WD + o] = m + convb[o];
    }
    const float* wr = wemb + (size_t)tok[w] * WD;
    for (int j = tid; j < WD; j += 128) d_z[(size_t)w * DD + j] = wr[j];
}

// ---------------- input-side GEMM, double-buffered smem, FFMA2 (R15 verified) -----
__global__ void __launch_bounds__(256, 2) k_gemm_gx(const float* __restrict__ Wf,
                                                    const float* __restrict__ biasf,
                                                    const float* __restrict__ Wb,
                                                    const float* __restrict__ biasb) {
    int dir = blockIdx.z;
    const float* __restrict__ Wm = dir ? Wb : Wf;
    const float* __restrict__ bias = dir ? biasb : biasf;
    float* out = d_gx[dir];
    const float* __restrict__ Z = d_z;

    int mBase = blockIdx.x * 128;
    int nBase = blockIdx.y * 64;

    __shared__ float As[2][16][132];
    __shared__ float Bs[2][16][68];

    int tid = threadIdx.x;
    int ty = tid >> 4;
    int tx = tid & 15;
    int ar = tid >> 2;       // 0..63
    int kq = tid & 3;        // 0..3

    const float* zp0 = Z + (size_t)(mBase + ar) * DD + kq * 4;
    const float* zp1 = Z + (size_t)(mBase + 64 + ar) * DD + kq * 4;
    const float* wp  = Wm + (size_t)(nBase + ar) * DD + kq * 4;

    unsigned long long acc2[8][2];
#pragma unroll
    for (int i = 0; i < 8; i++) { acc2[i][0] = 0ull; acc2[i][1] = 0ull; }

    float4 ra0, ra1, rb;
    // prologue: load tile 0
    ra0 = *(const float4*)(zp0);
    ra1 = *(const float4*)(zp1);
    rb  = *(const float4*)(wp);
    {
        As[0][kq * 4 + 0][ar] = ra0.x; As[0][kq * 4 + 1][ar] = ra0.y;
        As[0][kq * 4 + 2][ar] = ra0.z; As[0][kq * 4 + 3][ar] = ra0.w;
        As[0][kq * 4 + 0][64 + ar] = ra1.x; As[0][kq * 4 + 1][64 + ar] = ra1.y;
        As[0][kq * 4 + 2][64 + ar] = ra1.z; As[0][kq * 4 + 3][64 + ar] = ra1.w;
        Bs[0][kq * 4 + 0][ar] = rb.x; Bs[0][kq * 4 + 1][ar] = rb.y;
        Bs[0][kq * 4 + 2][ar] = rb.z; Bs[0][kq * 4 + 3][ar] = rb.w;
    }
    __syncthreads();

#pragma unroll 1
    for (int it = 0; it < DD / 16; it++) {
        int p = it & 1;
        if (it + 1 < DD / 16) {
            int k0 = 16 * (it + 1);
            ra0 = *(const float4*)(zp0 + k0);
            ra1 = *(const float4*)(zp1 + k0);
            rb  = *(const float4*)(wp + k0);
        }
#pragma unroll
        for (int kk = 0; kk < 16; kk++) {
            float4 a0 = *(const float4*)&As[p][kk][ty * 8];
            float4 a1 = *(const float4*)&As[p][kk][ty * 8 + 4];
            ulonglong2 bq = *(const ulonglong2*)&Bs[p][kk][tx * 4];
            float av[8] = {a0.x, a0.y, a0.z, a0.w, a1.x, a1.y, a1.z, a1.w};
#pragma unroll
            for (int i = 0; i < 8; i++) {
                unsigned long long ad = fdup(av[i]);
                ffma2(acc2[i][0], bq.x, ad);
                ffma2(acc2[i][1], bq.y, ad);
            }
        }
        if (it + 1 < DD / 16) {
            int q = p ^ 1;
            As[q][kq * 4 + 0][ar] = ra0.x; As[q][kq * 4 + 1][ar] = ra0.y;
            As[q][kq * 4 + 2][ar] = ra0.z; As[q][kq * 4 + 3][ar] = ra0.w;
            As[q][kq * 4 + 0][64 + ar] = ra1.x; As[q][kq * 4 + 1][64 + ar] = ra1.y;
            As[q][kq * 4 + 2][64 + ar] = ra1.z; As[q][kq * 4 + 3][64 + ar] = ra1.w;
            Bs[q][kq * 4 + 0][ar] = rb.x; Bs[q][kq * 4 + 1][ar] = rb.y;
            Bs[q][kq * 4 + 2][ar] = rb.z; Bs[q][kq * 4 + 3][ar] = rb.w;
        }
        __syncthreads();
    }

    float bq0 = bias[nBase + tx * 4 + 0], bq1 = bias[nBase + tx * 4 + 1];
    float bq2 = bias[nBase + tx * 4 + 2], bq3 = bias[nBase + tx * 4 + 3];
#pragma unroll
    for (int i = 0; i < 8; i++) {
        int m = mBase + ty * 8 + i;
        int b = m >> 9, s = m & 511;
        size_t ro = ((size_t)s * BB + b) * (size_t)G4 + nBase + tx * 4;
        float2 p0 = unpk(acc2[i][0]);
        float2 p1 = unpk(acc2[i][1]);
        float4 o4;
        o4.x = p0.x + bq0;
        o4.y = p0.y + bq1;
        o4.z = p1.x + bq2;
        o4.w = p1.y + bq3;
        *(float4*)&out[ro] = o4;
    }
}

// ---------------- BiLSTM: R14 (best verified) — unchanged -------------------------
#define NSL 16
#define KSL 16
__global__ void __launch_bounds__(256, 2)
k_lstm(const float* __restrict__ whf, const float* __restrict__ whb) {
    __shared__ float h_sm[2 * HH * 8];   // [parity][256 k][8 batch]
    __shared__ float g_sm[64 * 8];       // [local gate row][8 batch]
    __shared__ float c_sm[KSL * 8];      // [k*8+b]

    int blk = blockIdx.x;
    int slice = blk & (NSL - 1);
    int grp = blk >> 4;          // 0..15
    int dir = grp >> 3;
    int bg = grp & 7;
    const float* Wd = dir ? whb : whf;
    int tid = threadIdx.x;
    int row = tid >> 2;          // 0..63 local gate row
    int sub = tid & 3;           // k-interleave lane
    int gt = row >> 4;           // gate 0..3
    int kl = row & 15;
    int ks = slice * KSL;
    int gr = gt * 256 + ks + kl; // gate row in [0,1024)
    const float* gxp = d_gx[dir];
    float* hsp = d_hs[dir];
    int b0 = bg * 8;

    // W into registers: w_reg[kk] = W[gr][4*kk + sub]
    float w_reg[64];
    {
        const float* wr = Wd + (size_t)gr * HH + sub;
#pragma unroll
        for (int kk = 0; kk < 64; kk++) w_reg[kk] = __ldg(wr + 4 * kk);
    }
    if (tid < KSL * 8) c_sm[tid] = 0.f;
    __syncthreads();

    // preload gx for step 0 (sub==0 threads hold gxn for their row)
    float gxn[8];
    if (sub == 0) {
        int t0 = dir ? (SS - 1) : 0;
        const float* gxr = gxp + ((size_t)t0 * BB + b0) * G4 + gr;
#pragma unroll
        for (int b = 0; b < 8; b++) gxn[b] = __ldg(gxr + (size_t)b * G4);
    }

    for (int s = 0; s < SS; s++) {
        int t = dir ? (SS - 1 - s) : s;
        unsigned long long a0 = 0ull, a1 = 0ull, a2 = 0ull, a3 = 0ull;

        if (s > 0) {
            int parp = (s & 1) ^ 1;   // parity of step s-1
            // wait for all 16 CTAs of the group to finish step s-1
            if (tid == 0) {
                int tgt = NSL * s;
                while (acq_load(&d_ctr[grp]) < tgt) {}
            }
            __syncthreads();
            // load h(s-1) from L2 into smem (512 float4 by 256 threads)
            {
                const float4* src = (const float4*)(d_h2[grp][parp]);
                float* dst = h_sm + parp * (HH * 8);
                float4 v0 = __ldcg(src + tid);
                float4 v1 = __ldcg(src + tid + 256);
                *(float4*)&dst[tid * 4] = v0;
                *(float4*)&dst[(tid + 256) * 4] = v1;
            }
            __syncthreads();

            const float* hb = h_sm + parp * (HH * 8) + sub * 8;
#pragma unroll
            for (int kk = 0; kk < 64; kk++) {
                unsigned long long wd = fdup(w_reg[kk]);
                const ulonglong2* hp = (const ulonglong2*)(hb + kk * 32);
                ulonglong2 q0 = hp[0];   // batches 0,1 | 2,3
                ulonglong2 q1 = hp[1];   // batches 4,5 | 6,7
                ffma2(a0, q0.x, wd);
                ffma2(a1, q0.y, wd);
                ffma2(a2, q1.x, wd);
                ffma2(a3, q1.y, wd);
            }
            // reduce across the 4 sub lanes (adjacent in warp)
            a0 = addx2(a0, __shfl_xor_sync(0xffffffffu, a0, 1));
            a1 = addx2(a1, __shfl_xor_sync(0xffffffffu, a1, 1));
            a2 = addx2(a2, __shfl_xor_sync(0xffffffffu, a2, 1));
            a3 = addx2(a3, __shfl_xor_sync(0xffffffffu, a3, 1));
            a0 = addx2(a0, __shfl_xor_sync(0xffffffffu, a0, 2));
            a1 = addx2(a1, __shfl_xor_sync(0xffffffffu, a1, 2));
            a2 = addx2(a2, __shfl_xor_sync(0xffffffffu, a2, 2));
            a3 = addx2(a3, __shfl_xor_sync(0xffffffffu, a3, 2));
        }
        if (sub == 0) {
            float2 p0 = unpk(a0), p1 = unpk(a1), p2 = unpk(a2), p3 = unpk(a3);
            float4 v0, v1;
            v0.x = p0.x + gxn[0]; v0.y = p0.y + gxn[1];
            v0.z = p1.x + gxn[2]; v0.w = p1.y + gxn[3];
            v1.x = p2.x + gxn[4]; v1.y = p2.y + gxn[5];
            v1.z = p3.x + gxn[6]; v1.w = p3.y + gxn[7];
            *(float4*)&g_sm[row * 8] = v0;
            *(float4*)&g_sm[row * 8 + 4] = v1;
        }
        __syncthreads();

        // elementwise LSTM cell: 128 tasks (k = tid>>3 in [0,16), b = tid&7)
        int par = s & 1;
        float hv = 0.f;
        if (tid < KSL * 8) {
            int k = tid >> 3;
            int b = tid & 7;
            float gi = g_sm[(0 * KSL + k) * 8 + b];
            float gf = g_sm[(1 * KSL + k) * 8 + b];
            float gg = g_sm[(2 * KSL + k) * 8 + b];
            float go = g_sm[(3 * KSL + k) * 8 + b];
            float c = c_sm[tid];
            float cn = sigf(gf) * c + sigf(gi) * tanhf(gg);
            hv = sigf(go) * tanhf(cn);
            c_sm[tid] = cn;
            __stcg(&d_h2[grp][par][(ks + k) * 8 + b], hv);
        }
        // prefetch next step's gx (independent of the barrier)
        if (sub == 0 && s + 1 < SS) {
            int tn = dir ? (SS - 2 - s) : (s + 1);
            const float* gxr = gxp + ((size_t)tn * BB + b0) * G4 + gr;
#pragma unroll
            for (int b = 0; b < 8; b++) gxn[b] = __ldg(gxr + (size_t)b * G4);
        }
        __syncthreads();   // h2 stores issued by all cell threads before publish
        if (tid == 0) red_release_add(&d_ctr[grp], 1);
        // history write AFTER publish — background stream, never fenced
        if (tid < KSL * 8) {
            int k = tid >> 3;
            int b = tid & 7;
            hsp[((size_t)t * BB + b0 + b) * HH + ks + k] = hv;
        }
    }
}

// ---------------- emissions: concat(hs_f, hs_b) @ cls_w^T + cls_b ----------------
__global__ void __launch_bounds__(256) k_emis(const float* __restrict__ clsw,
                                              const float* __restrict__ clsb) {
    __shared__ float cw[TT * 512];
    __shared__ float cb[32];
    int tid = threadIdx.x;
    for (int i = tid; i < TT * 512; i += 256) cw[i] = clsw[i];
    if (tid < TT) cb[tid] = clsb[tid];
    __syncthreads();

    int warp = tid >> 5, lane = tid & 31;
    int w = blockIdx.x * 8 + warp;
    int b = w >> 9, s = w & 511;
    const float* hf = d_hs[0] + ((size_t)s * BB + b) * HH;
    const float* hb = d_hs[1] + ((size_t)s * BB + b) * HH;
    float hv[16];
#pragma unroll
    for (int i = 0; i < 8; i++) {
        hv[i] = hf[lane + 32 * i];
        hv[8 + i] = hb[lane + 32 * i];
    }
#pragma unroll 1
    for (int o = 0; o < TT; o++) {
        const float* c0 = cw + o * 512;
        float sum = 0.f;
#pragma unroll
        for (int i = 0; i < 8; i++) {
            sum = fmaf(hv[i], c0[lane + 32 * i], sum);
            sum = fmaf(hv[8 + i], c0[256 + lane + 32 * i], sum);
        }
#pragma unroll
        for (int off = 16; off > 0; off >>= 1)
            sum += __shfl_down_sync(0xffffffffu, sum, off);
        if (lane == 0) d_emis[(size_t)w * TT + o] = sum + cb[o];
    }
}

// ---------------- CRF: blocks 0..63 = loss forward, 64..127 = Viterbi decode -------
__global__ void __launch_bounds__(32) k_crf(const int* __restrict__ labels,
                                            const int* __restrict__ mask,
                                            const float* __restrict__ startt,
                                            const float* __restrict__ endt,
                                            const float* __restrict__ trans,
                                            float* __restrict__ tok_out) {
    int which = blockIdx.x >> 6;
    int b = blockIdx.x & 63;
    int ln = threadIdx.x;
    __shared__ float tr[TT * TT];
    __shared__ float al[TT];
    __shared__ unsigned char bp[SS - 1][TT];
    for (int i = ln; i < TT * TT; i += 32) tr[i] = trans[i];
    __syncwarp();

    if (which == 0) {
        // ---- loss ----
        float part = 0.f;
        for (int s = ln; s < SS; s += 32) {
            int tg = labels[(size_t)b * SS + s];
            float mf = (float)mask[(size_t)b * SS + s];
            part += d_emis[((size_t)b * SS + s) * TT + tg] * mf;
            if (s >= 1) {
                int tp = labels[(size_t)b * SS + s - 1];
                part += tr[tp * TT + tg] * mf;
            }
        }
#pragma unroll
        for (int off = 16; off > 0; off >>= 1)
            part += __shfl_down_sync(0xffffffffu, part, off);
        float num = 0.f;
        if (ln == 0) {
            num = part + startt[labels[(size_t)b * SS]];
            int cnt = 0;
            for (int s = 0; s < SS; s++) cnt += mask[(size_t)b * SS + s];
            num += endt[labels[(size_t)b * SS + cnt - 1]];
        }

        if (ln < TT) al[ln] = startt[ln] + d_emis[((size_t)b * SS) * TT + ln];
        __syncwarp();
        for (int s = 1; s < SS; s++) {
            int m = mask[(size_t)b * SS + s];
            float nv = 0.f;
            if (ln < TT) {
                float v[TT];
                float mx = -1e30f;
#pragma unroll
                for (int i = 0; i < TT; i++) {
                    v[i] = al[i] + tr[i * TT + ln];
                    mx = fmaxf(mx, v[i]);
                }
                float sum = 0.f;
#pragma unroll
                for (int i = 0; i < TT; i++) sum += expf(v[i] - mx);
                nv = mx + logf(sum) + d_emis[((size_t)b * SS + s) * TT + ln];
            }
            __syncwarp();
            if (ln < TT && m > 0) al[ln] = nv;
            __syncwarp();
        }
        if (ln == 0) {
            float mx = -1e30f;
            for (int j = 0; j < TT; j++) mx = fmaxf(mx, al[j] + endt[j]);
            float sum = 0.f;
            for (int j = 0; j < TT; j++) sum += expf(al[j] + endt[j] - mx);
            d_nd[b] = num - (mx + logf(sum));
        }
    } else {
        // ---- Viterbi decode ----
        if (ln < TT) al[ln] = startt[ln] + d_emis[((size_t)b * SS) * TT + ln];
        __syncwarp();
        for (int s = 1; s < SS; s++) {
            int m = mask[(size_t)b * SS + s];
            float nv = 0.f;
            int arg = 0;
            if (ln < TT) {
                float mx = -1e30f;
#pragma unroll
                for (int i = 0; i < TT; i++) {
                    float v = al[i] + tr[i * TT + ln];
                    if (v > mx) { mx = v; arg = i; }
                }
                nv = mx + d_emis[((size_t)b * SS + s) * TT + ln];
            }
            __syncwarp();
            if (ln < TT) {
                if (m > 0) { al[ln] = nv; bp[s - 1][ln] = (unsigned char)arg; }
                else bp[s - 1][ln] = (unsigned char)ln;
            }
            __syncwarp();
        }
        if (ln == 0) {
            float mx = -1e30f;
            int lt = 0;
            for (int j = 0; j < TT; j++) {
                float v = al[j] + endt[j];
                if (v > mx) { mx = v; lt = j; }
            }
            tok_out[(size_t)b * SS + (SS - 1)] = (float)lt;
            int tg = lt;
            for (int s = SS - 2; s >= 0; s--) {
                tg = bp[s][tg];
                tok_out[(size_t)b * SS + s] = (float)tg;
            }
        }
    }
}

// ---------------- final loss reduce ----------------
__global__ void __launch_bounds__(64) k_final(float* __restrict__ out) {
    int tid = threadIdx.x;
    float v = d_nd[tid];
#pragma unroll
    for (int off = 16; off > 0; off >>= 1) v += __shfl_down_sync(0xffffffffu, v, off);
    __shared__ float w[2];
    if ((tid & 31) == 0) w[tid >> 5] = v;
    __syncthreads();
    if (tid == 0) out[0] = -(w[0] + w[1]) / (float)BB;
}

// ---------------- launch ----------------
extern "C" void kernel_launch(void* const* d_in, const int* in_sizes, int n_in,
                              void* d_out, int out_size) {
    const int* tok     = (const int*)d_in[0];
    const int* ctok    = (const int*)d_in[1];
    const int* labels  = (const int*)d_in[2];
    const int* amask   = (const int*)d_in[3];
    const float* wemb  = (const float*)d_in[4];
    const float* cemb  = (const float*)d_in[5];
    const float* convw = (const float*)d_in[6];
    const float* convb = (const float*)d_in[7];
    const float* wihf  = (const float*)d_in[8];
    const float* whhf  = (const float*)d_in[9];
    const float* bf    = (const float*)d_in[10];
    const float* wihb  = (const float*)d_in[11];
    const float* whhb  = (const float*)d_in[12];
    const float* bb    = (const float*)d_in[13];
    const float* clsw  = (const float*)d_in[14];
    const float* clsb  = (const float*)d_in[15];
    const float* startt = (const float*)d_in[16];
    const float* endt   = (const float*)d_in[17];
    const float* trans  = (const float*)d_in[18];
    float* out = (float*)d_out;
    int tok_off = out_size - BB * SS;
    if (tok_off < 0) tok_off = 0;

    k_embed<<<BS / 2, 256>>>(tok, ctok, wemb, cemb, convw, convb);
    dim3 gg(BS / 128, G4 / 64, 2);
    k_gemm_gx<<<gg, 256>>>(wihf, bf, wihb, bb);
    k_lstm<<<256, 256>>>(whhf, whhb);
    k_emis<<<BS / 8, 256>>>(clsw, clsb);
    k_crf<<<2 * BB, 32>>>(labels, amask, startt, endt, trans, out + tok_off);
    k_final<<<1, 64>>>(out);
}